// round 9
// baseline (speedup 1.0000x reference)
#include <cuda_runtime.h>
#include <cuda_bf16.h>
#include <math.h>

// ---------------------------------------------------------------------------
// Problem constants
// ---------------------------------------------------------------------------
#define BD   8
#define CD   512
#define ND   4096          // H*W tokens per batch
#define NHD  8
#define DDIM 64
#define NTOK (BD * ND)     // 32768

// ---------------------------------------------------------------------------
// Scratch: __device__ globals (allocation-free)
// ---------------------------------------------------------------------------
__device__ float  g_qnorm [NTOK * CD];   // (B*N, C) LN'ed q
__device__ float  g_kvnorm[NTOK * CD];   // (B*N, C) LN'ed kv
__device__ float  g_Qp    [NTOK * CD];   // (B*N, C) projected Q (rope applied in place)
__device__ float  g_Kp    [NTOK * CD];
__device__ float  g_Vp    [NTOK * CD];
__device__ float  g_attn  [NTOK * CD];   // attention output (B*N, C), C = head-concat
__device__ float  g_proj  [NTOK * CD];   // O-projection + residual
__device__ float2 g_rope  [ND * 32];     // (pos, i) -> (sin, cos)
__device__ float  g_biasM [NHD * 64 * 64]; // (h, q, k) expanded rel-pos bias

// ---------------------------------------------------------------------------
// Packed f32x2 FMA (sm_100+)
// ---------------------------------------------------------------------------
union f2u { float2 f; unsigned long long u; };

__device__ __forceinline__ unsigned long long ffma2(unsigned long long a,
                                                    unsigned long long b,
                                                    unsigned long long c) {
    unsigned long long d;
    asm("fma.rn.f32x2 %0, %1, %2, %3;" : "=l"(d) : "l"(a), "l"(b), "l"(c));
    return d;
}

// ---------------------------------------------------------------------------
// Precompute: RoPE cache + expanded bias matrix
// grid 512 x 256 threads -> t in [0, 131072)
// ---------------------------------------------------------------------------
__global__ __launch_bounds__(256) void precompute_kernel(const float* __restrict__ bt) {
    __shared__ float invf[32];
    if (threadIdx.x < 32)
        invf[threadIdx.x] = (float)(1.0 / pow(10000.0, (double)threadIdx.x / 32.0));
    __syncthreads();

    int t = blockIdx.x * 256 + threadIdx.x;
    // rope: pos in [0,4096), i in [0,32)
    {
        int pos = t >> 5, i = t & 31;
        float ang = (float)pos * invf[i];          // match reference fp32 rounding
        g_rope[t] = make_float2(sinf(ang), cosf(ang));
    }
    // bias matrix: 8*64*64 = 32768
    if (t < NHD * 64 * 64) {
        int h = t >> 12, q = (t >> 6) & 63, k = t & 63;
        int dr = (q >> 3) - (k >> 3) + 7;
        int dc = (q & 7) - (k & 7) + 7;
        g_biasM[t] = bt[(dr * 15 + dc) * NHD + h];
    }
}

// ---------------------------------------------------------------------------
// LayerNorm over C per token; input NCHW (B,C,N) -> output token-major (B*N, C)
// Block: 256 thr, tile = 16 tokens x 512 channels. Grid = B*256 = 2048.
// ---------------------------------------------------------------------------
__global__ __launch_bounds__(256) void ln_kernel(const float* __restrict__ x,
                                                 const float* __restrict__ gam,
                                                 const float* __restrict__ bet,
                                                 float* __restrict__ out) {
    __shared__ float tile[16][513];
    __shared__ float smu[16], srs[16];

    int blk = blockIdx.x;
    int b   = blk >> 8;
    int n0  = (blk & 255) << 4;
    const float* xb = x + (size_t)b * CD * ND;
    int t = threadIdx.x;
    int tok = t & 15, cb = t >> 4;

#pragma unroll
    for (int k = 0; k < 32; k++) {
        int c = cb + (k << 4);
        tile[tok][c] = xb[(size_t)c * ND + n0 + tok];
    }
    __syncthreads();

    int lane = t & 31, w = t >> 5;
#pragma unroll
    for (int s = 0; s < 2; s++) {
        int tr = w * 2 + s;
        float sum = 0.f;
#pragma unroll
        for (int j = 0; j < 16; j++) sum += tile[tr][lane + 32 * j];
#pragma unroll
        for (int o = 16; o > 0; o >>= 1) sum += __shfl_xor_sync(~0u, sum, o);
        float mu = sum * (1.0f / 512.0f);
        float vs = 0.f;
#pragma unroll
        for (int j = 0; j < 16; j++) {
            float d = tile[tr][lane + 32 * j] - mu;
            vs += d * d;
        }
#pragma unroll
        for (int o = 16; o > 0; o >>= 1) vs += __shfl_xor_sync(~0u, vs, o);
        if (lane == 0) {
            smu[tr] = mu;
            srs[tr] = rsqrtf(vs * (1.0f / 512.0f) + 1e-5f);
        }
    }
    __syncthreads();

    for (int idx = t; idx < 16 * 512; idx += 256) {
        int tk = idx >> 9, c = idx & 511;
        float v = (tile[tk][c] - smu[tk]) * srs[tk] * gam[c] + bet[c];
        out[(size_t)(b * ND + n0 + tk) * CD + c] = v;
    }
}

// ---------------------------------------------------------------------------
// SGEMM: C[M,512] = A[M,512] * W^T + bias (+ resid). W is (512,512) row-major (o,k).
// Block tile 128x128, BK=16, 256 threads, 8x8 microtile, FFMA2.
// Grid: (M/128, 4).
// ---------------------------------------------------------------------------
template <bool RESID>
__global__ __launch_bounds__(256) void sgemm_kernel(const float* __restrict__ A,
                                                    const float* __restrict__ W,
                                                    const float* __restrict__ bias,
                                                    const float* __restrict__ resid,
                                                    float* __restrict__ C) {
    __shared__ float As[16][132];
    __shared__ float Bs[16][132];

    int m0 = blockIdx.x * 128;
    int n0 = blockIdx.y * 128;
    int t  = threadIdx.x;
    int tx = t & 15, ty = t >> 4;
    int am = t >> 2;            // 0..63
    int ak = (t & 3) * 4;       // 0,4,8,12

    const float* Ap = A + (size_t)(m0 + am) * 512 + ak;
    const float* Wp = W + (size_t)(n0 + am) * 512 + ak;

    float4 ra0, ra1, rb0, rb1;
    ra0 = *(const float4*)(Ap);
    ra1 = *(const float4*)(Ap + (size_t)64 * 512);
    rb0 = *(const float4*)(Wp);
    rb1 = *(const float4*)(Wp + (size_t)64 * 512);

    f2u acc[8][4];
#pragma unroll
    for (int i = 0; i < 8; i++)
#pragma unroll
        for (int j = 0; j < 4; j++) acc[i][j].f = make_float2(0.f, 0.f);

    // stage regs -> smem
    {
        As[ak + 0][am] = ra0.x; As[ak + 1][am] = ra0.y; As[ak + 2][am] = ra0.z; As[ak + 3][am] = ra0.w;
        As[ak + 0][am + 64] = ra1.x; As[ak + 1][am + 64] = ra1.y; As[ak + 2][am + 64] = ra1.z; As[ak + 3][am + 64] = ra1.w;
        Bs[ak + 0][am] = rb0.x; Bs[ak + 1][am] = rb0.y; Bs[ak + 2][am] = rb0.z; Bs[ak + 3][am] = rb0.w;
        Bs[ak + 0][am + 64] = rb1.x; Bs[ak + 1][am + 64] = rb1.y; Bs[ak + 2][am + 64] = rb1.z; Bs[ak + 3][am + 64] = rb1.w;
    }
    __syncthreads();

    for (int ks = 1; ks <= 32; ks++) {
        if (ks < 32) {
            ra0 = *(const float4*)(Ap + ks * 16);
            ra1 = *(const float4*)(Ap + (size_t)64 * 512 + ks * 16);
            rb0 = *(const float4*)(Wp + ks * 16);
            rb1 = *(const float4*)(Wp + (size_t)64 * 512 + ks * 16);
        }
#pragma unroll
        for (int kk = 0; kk < 16; kk++) {
            float4 a0 = *(const float4*)&As[kk][ty * 4];
            float4 a1 = *(const float4*)&As[kk][64 + ty * 4];
            float4 b0 = *(const float4*)&Bs[kk][tx * 4];
            float4 b1 = *(const float4*)&Bs[kk][64 + tx * 4];
            f2u bb[4];
            bb[0].f = make_float2(b0.x, b0.y);
            bb[1].f = make_float2(b0.z, b0.w);
            bb[2].f = make_float2(b1.x, b1.y);
            bb[3].f = make_float2(b1.z, b1.w);
            float av[8] = {a0.x, a0.y, a0.z, a0.w, a1.x, a1.y, a1.z, a1.w};
#pragma unroll
            for (int i = 0; i < 8; i++) {
                f2u a2; a2.f = make_float2(av[i], av[i]);
#pragma unroll
                for (int j = 0; j < 4; j++)
                    acc[i][j].u = ffma2(a2.u, bb[j].u, acc[i][j].u);
            }
        }
        if (ks < 32) {
            __syncthreads();
            As[ak + 0][am] = ra0.x; As[ak + 1][am] = ra0.y; As[ak + 2][am] = ra0.z; As[ak + 3][am] = ra0.w;
            As[ak + 0][am + 64] = ra1.x; As[ak + 1][am + 64] = ra1.y; As[ak + 2][am + 64] = ra1.z; As[ak + 3][am + 64] = ra1.w;
            Bs[ak + 0][am] = rb0.x; Bs[ak + 1][am] = rb0.y; Bs[ak + 2][am] = rb0.z; Bs[ak + 3][am] = rb0.w;
            Bs[ak + 0][am + 64] = rb1.x; Bs[ak + 1][am + 64] = rb1.y; Bs[ak + 2][am + 64] = rb1.z; Bs[ak + 3][am + 64] = rb1.w;
            __syncthreads();
        }
    }

    // epilogue
#pragma unroll
    for (int half = 0; half < 2; half++) {
        int col = n0 + half * 64 + tx * 4;
        float4 bb4 = *(const float4*)&bias[col];
#pragma unroll
        for (int i = 0; i < 8; i++) {
            int row = m0 + ((i < 4) ? (ty * 4 + i) : (64 + ty * 4 + i - 4));
            float2 p0 = acc[i][half * 2 + 0].f;
            float2 p1 = acc[i][half * 2 + 1].f;
            float4 v = make_float4(p0.x + bb4.x, p0.y + bb4.y, p1.x + bb4.z, p1.y + bb4.w);
            if (RESID) {
                float4 r = *(const float4*)&resid[(size_t)row * 512 + col];
                v.x += r.x; v.y += r.y; v.z += r.z; v.w += r.w;
            }
            *(float4*)&C[(size_t)row * 512 + col] = v;
        }
    }
}

// ---------------------------------------------------------------------------
// RoPE in place on Q and K, (B*N, C) layout, pairs along c within each head.
// grid (32768, 2) x 256 threads; one float2 pair per thread.
// ---------------------------------------------------------------------------
__global__ __launch_bounds__(256) void rope_kernel() {
    size_t t = (size_t)blockIdx.x * 256 + threadIdx.x;   // 0 .. 8388607
    int tok = (int)(t >> 8);
    int p   = (int)(t & 255);
    int i   = p & 31;
    int pos = tok & (ND - 1);
    float2 rc = g_rope[pos * 32 + i];     // (sin, cos)
    float2* base = (float2*)(blockIdx.y ? g_Kp : g_Qp);
    float2 x = base[t];
    float2 y;
    y.x = x.x * rc.y - x.y * rc.x;
    y.y = x.x * rc.x + x.y * rc.y;
    base[t] = y;
}

// ---------------------------------------------------------------------------
// Windowed attention. grid (64 windows, NH, B), 256 threads.
// Quad-per-row: thread (q = t>>2, j = t&3); S/P in registers.
// dyn smem: Q,K,V tiles 64 x 68 floats each (Q reused for P).
// ---------------------------------------------------------------------------
__global__ __launch_bounds__(256) void attn_kernel() {
    extern __shared__ float sm[];
    float* Qs = sm;
    float* Ks = sm + 64 * 68;
    float* Vs = sm + 2 * 64 * 68;

    int w = blockIdx.x, h = blockIdx.y, b = blockIdx.z;
    int wy = w >> 3, wx = w & 7;
    size_t base = (size_t)b * ND * CD + (size_t)h * 64;
    const float* Qg = g_Qp + base;
    const float* Kg = g_Kp + base;
    const float* Vg = g_Vp + base;

    int t = threadIdx.x;
#pragma unroll
    for (int it = 0; it < 4; it++) {
        int idx = t + it * 256;
        int r = idx >> 4, c4 = idx & 15;
        int n = (wy * 8 + (r >> 3)) * 64 + wx * 8 + (r & 7);
        size_t ga = (size_t)n * CD + c4 * 4;
        *(float4*)&Qs[r * 68 + c4 * 4] = *(const float4*)&Qg[ga];
        *(float4*)&Ks[r * 68 + c4 * 4] = *(const float4*)&Kg[ga];
        *(float4*)&Vs[r * 68 + c4 * 4] = *(const float4*)&Vg[ga];
    }
    __syncthreads();

    int q = t >> 2, j = t & 3;
    float s[16];
#pragma unroll
    for (int i = 0; i < 16; i++) s[i] = 0.f;

    // S = Q K^T  (thread owns k = 4i + j, i = 0..15)
#pragma unroll
    for (int ch = 0; ch < 4; ch++) {
        float4 qv[4];
#pragma unroll
        for (int c = 0; c < 4; c++)
            qv[c] = *(float4*)&Qs[q * 68 + ch * 16 + c * 4];
#pragma unroll
        for (int i = 0; i < 16; i++) {
            int k = i * 4 + j;
            const float* kr = &Ks[k * 68 + ch * 16];
            float4 k0 = *(float4*)&kr[0];
            float4 k1 = *(float4*)&kr[4];
            float4 k2 = *(float4*)&kr[8];
            float4 k3 = *(float4*)&kr[12];
            s[i] += qv[0].x * k0.x + qv[0].y * k0.y + qv[0].z * k0.z + qv[0].w * k0.w
                  + qv[1].x * k1.x + qv[1].y * k1.y + qv[1].z * k1.z + qv[1].w * k1.w
                  + qv[2].x * k2.x + qv[2].y * k2.y + qv[2].z * k2.z + qv[2].w * k2.w
                  + qv[3].x * k3.x + qv[3].y * k3.y + qv[3].z * k3.z + qv[3].w * k3.w;
        }
    }

    // bias + softmax (quad reduction via shfl_xor 1,2)
    const float* brow = g_biasM + h * 4096 + q * 64;
    float mx = -1e30f;
#pragma unroll
    for (int i = 0; i < 16; i++) {
        s[i] = s[i] * 0.125f + __ldg(&brow[i * 4 + j]);
        mx = fmaxf(mx, s[i]);
    }
    mx = fmaxf(mx, __shfl_xor_sync(~0u, mx, 1));
    mx = fmaxf(mx, __shfl_xor_sync(~0u, mx, 2));
    float sum = 0.f;
#pragma unroll
    for (int i = 0; i < 16; i++) {
        s[i] = __expf(s[i] - mx);
        sum += s[i];
    }
    sum += __shfl_xor_sync(~0u, sum, 1);
    sum += __shfl_xor_sync(~0u, sum, 2);
    float inv = 1.0f / sum;

    __syncthreads();             // all QK reads of Qs done
#pragma unroll
    for (int i = 0; i < 16; i++)
        Qs[q * 68 + i * 4 + j] = s[i] * inv;   // P tile reuses Qs
    __syncthreads();

    // O = P V  (thread owns d = 16*ii + 4*j + 0..3, ii = 0..3)
    float4 o[4];
#pragma unroll
    for (int ii = 0; ii < 4; ii++) o[ii] = make_float4(0.f, 0.f, 0.f, 0.f);
#pragma unroll
    for (int k = 0; k < 64; k++) {
        float p = Qs[q * 68 + k];
        const float* vr = &Vs[k * 68];
#pragma unroll
        for (int ii = 0; ii < 4; ii++) {
            float4 v = *(float4*)&vr[ii * 16 + j * 4];
            o[ii].x += p * v.x; o[ii].y += p * v.y;
            o[ii].z += p * v.z; o[ii].w += p * v.w;
        }
    }

    float* Ob = g_attn + base;
    int n = (wy * 8 + (q >> 3)) * 64 + wx * 8 + (q & 7);
#pragma unroll
    for (int ii = 0; ii < 4; ii++)
        *(float4*)&Ob[(size_t)n * CD + ii * 16 + j * 4] = o[ii];
}

// ---------------------------------------------------------------------------
// Final transpose (B, N, C) -> (B, C, N)
// grid (N/32, C/32, B), block (32, 8)
// ---------------------------------------------------------------------------
__global__ __launch_bounds__(256) void transpose_kernel(const float* __restrict__ in,
                                                        float* __restrict__ out) {
    __shared__ float tile[32][33];
    int b  = blockIdx.z;
    int n0 = blockIdx.x * 32;
    int c0 = blockIdx.y * 32;
    int tx = threadIdx.x, ty = threadIdx.y;
#pragma unroll
    for (int r = 0; r < 4; r++)
        tile[ty + r * 8][tx] = in[(size_t)(b * ND + n0 + ty + r * 8) * CD + c0 + tx];
    __syncthreads();
#pragma unroll
    for (int r = 0; r < 4; r++)
        out[(size_t)(b * CD + c0 + ty + r * 8) * ND + n0 + tx] = tile[tx][ty + r * 8];
}

// ---------------------------------------------------------------------------
// Launch
// ---------------------------------------------------------------------------
extern "C" void kernel_launch(void* const* d_in, const int* in_sizes, int n_in,
                              void* d_out, int out_size) {
    const float* q       = (const float*)d_in[0];
    const float* kv      = (const float*)d_in[1];
    const float* g_q     = (const float*)d_in[2];
    const float* b_q_ln  = (const float*)d_in[3];
    const float* g_kv    = (const float*)d_in[4];
    const float* b_kv_ln = (const float*)d_in[5];
    const float* Wq      = (const float*)d_in[6];
    const float* bq      = (const float*)d_in[7];
    const float* Wk      = (const float*)d_in[8];
    const float* bk      = (const float*)d_in[9];
    const float* Wv      = (const float*)d_in[10];
    const float* bv      = (const float*)d_in[11];
    const float* Wo      = (const float*)d_in[12];
    const float* bo      = (const float*)d_in[13];
    const float* btab    = (const float*)d_in[14];
    float* out = (float*)d_out;

    float *qn, *kvn, *Qp, *Kp, *Vp, *att, *proj;
    cudaGetSymbolAddress((void**)&qn,   g_qnorm);
    cudaGetSymbolAddress((void**)&kvn,  g_kvnorm);
    cudaGetSymbolAddress((void**)&Qp,   g_Qp);
    cudaGetSymbolAddress((void**)&Kp,   g_Kp);
    cudaGetSymbolAddress((void**)&Vp,   g_Vp);
    cudaGetSymbolAddress((void**)&att,  g_attn);
    cudaGetSymbolAddress((void**)&proj, g_proj);

    // 1. precompute rope cache + bias matrix
    precompute_kernel<<<512, 256>>>(btab);

    // 2. LayerNorm q, kv
    ln_kernel<<<2048, 256>>>(q,  g_q,  b_q_ln,  qn);
    ln_kernel<<<2048, 256>>>(kv, g_kv, b_kv_ln, kvn);

    // 3. QKV projections
    dim3 ggrid(NTOK / 128, 4);
    sgemm_kernel<false><<<ggrid, 256>>>(qn,  Wq, bq, nullptr, Qp);
    sgemm_kernel<false><<<ggrid, 256>>>(kvn, Wk, bk, nullptr, Kp);
    sgemm_kernel<false><<<ggrid, 256>>>(kvn, Wv, bv, nullptr, Vp);

    // 4. RoPE on Q and K (in place)
    rope_kernel<<<dim3(NTOK * CD / 2 / 256, 2), 256>>>();

    // 5. windowed attention
    int smem = 3 * 64 * 68 * (int)sizeof(float);   // 52224 B > 48KB default
    cudaFuncSetAttribute(attn_kernel, cudaFuncAttributeMaxDynamicSharedMemorySize, smem);
    attn_kernel<<<dim3(64, NHD, BD), 256, smem>>>();

    // 6. output projection + residual with normed q
    sgemm_kernel<true><<<ggrid, 256>>>(att, Wo, bo, qn, proj);

    // 7. (B,N,C) -> (B,C,H,W)
    transpose_kernel<<<dim3(ND / 32, CD / 32, BD), dim3(32, 8)>>>(proj, out);
}

// round 13
// speedup vs baseline: 1.8210x; 1.8210x over previous
#include <cuda_runtime.h>
#include <cuda_bf16.h>
#include <math.h>
#include <stdint.h>

// ---------------------------------------------------------------------------
// Problem constants
// ---------------------------------------------------------------------------
#define BD   8
#define CD   512
#define ND   4096          // H*W tokens per batch
#define NHD  8
#define DDIM 64
#define NTOK (BD * ND)     // 32768

// ---------------------------------------------------------------------------
// Scratch: __device__ globals (allocation-free)
// ---------------------------------------------------------------------------
__device__ float  g_qnorm [NTOK * CD];   // (B*N, C) LN'ed q
__device__ float  g_kvnorm[NTOK * CD];   // (B*N, C) LN'ed kv
__device__ float  g_Qp    [NTOK * CD];   // projected Q (rope fused in epilogue)
__device__ float  g_Kp    [NTOK * CD];
__device__ float  g_Vp    [NTOK * CD];
__device__ float  g_attn  [NTOK * CD];   // attention output (B*N, C)
__device__ float  g_proj  [NTOK * CD];   // O-projection + residual
__device__ float2 g_rope  [ND * 32];     // (pos, i) -> (sin, cos)
__device__ float  g_biasM [NHD * 64 * 64]; // (h, q, k) expanded rel-pos bias

// ---------------------------------------------------------------------------
// PTX helpers (compute_103-safe: sm_80 era tensor ops only)
// ---------------------------------------------------------------------------
__device__ __forceinline__ uint32_t smem_u32(const void* p) {
    uint32_t a;
    asm("{ .reg .u64 t; cvta.to.shared.u64 t, %1; cvt.u32.u64 %0, t; }"
        : "=r"(a) : "l"(p));
    return a;
}

__device__ __forceinline__ uint32_t f2tf32(float x) {
    uint32_t r;
    asm("cvt.rna.tf32.f32 %0, %1;" : "=r"(r) : "f"(x));
    return r;
}

__device__ __forceinline__ void sts128(uint32_t addr, uint32_t a, uint32_t b,
                                       uint32_t c, uint32_t d) {
    asm volatile("st.shared.v4.b32 [%0], {%1,%2,%3,%4};"
                 :: "r"(addr), "r"(a), "r"(b), "r"(c), "r"(d) : "memory");
}

__device__ __forceinline__ void ldsm4(uint32_t* r, uint32_t addr) {
    asm volatile("ldmatrix.sync.aligned.m8n8.x4.shared.b16 {%0,%1,%2,%3}, [%4];"
                 : "=r"(r[0]), "=r"(r[1]), "=r"(r[2]), "=r"(r[3]) : "r"(addr));
}

__device__ __forceinline__ void mma_tf32(float* d, const uint32_t* a, const uint32_t* b) {
    asm volatile(
        "mma.sync.aligned.m16n8k8.row.col.f32.tf32.tf32.f32 "
        "{%0,%1,%2,%3}, {%4,%5,%6,%7}, {%8,%9}, {%0,%1,%2,%3};"
        : "+f"(d[0]), "+f"(d[1]), "+f"(d[2]), "+f"(d[3])
        : "r"(a[0]), "r"(a[1]), "r"(a[2]), "r"(a[3]), "r"(b[0]), "r"(b[1]));
}

// ---------------------------------------------------------------------------
// Precompute: RoPE cache + expanded bias matrix
// ---------------------------------------------------------------------------
__global__ __launch_bounds__(256) void precompute_kernel(const float* __restrict__ bt) {
    __shared__ float invf[32];
    if (threadIdx.x < 32)
        invf[threadIdx.x] = (float)(1.0 / pow(10000.0, (double)threadIdx.x / 32.0));
    __syncthreads();

    int t = blockIdx.x * 256 + threadIdx.x;
    {
        int pos = t >> 5, i = t & 31;
        float ang = (float)pos * invf[i];
        g_rope[t] = make_float2(sinf(ang), cosf(ang));
    }
    if (t < NHD * 64 * 64) {
        int h = t >> 12, q = (t >> 6) & 63, k = t & 63;
        int dr = (q >> 3) - (k >> 3) + 7;
        int dc = (q & 7) - (k & 7) + 7;
        g_biasM[t] = bt[(dr * 15 + dc) * NHD + h];
    }
}

// ---------------------------------------------------------------------------
// LayerNorm over C per token; NCHW (B,C,N) -> token-major (B*N, C)
// ---------------------------------------------------------------------------
__global__ __launch_bounds__(256) void ln_kernel(const float* __restrict__ x,
                                                 const float* __restrict__ gam,
                                                 const float* __restrict__ bet,
                                                 float* __restrict__ out) {
    __shared__ float tile[16][513];
    __shared__ float smu[16], srs[16];

    int blk = blockIdx.x;
    int b   = blk >> 8;
    int n0  = (blk & 255) << 4;
    const float* xb = x + (size_t)b * CD * ND;
    int t = threadIdx.x;
    int tok = t & 15, cb = t >> 4;

#pragma unroll
    for (int k = 0; k < 32; k++) {
        int c = cb + (k << 4);
        tile[tok][c] = xb[(size_t)c * ND + n0 + tok];
    }
    __syncthreads();

    int lane = t & 31, w = t >> 5;
#pragma unroll
    for (int s = 0; s < 2; s++) {
        int tr = w * 2 + s;
        float sum = 0.f;
#pragma unroll
        for (int j = 0; j < 16; j++) sum += tile[tr][lane + 32 * j];
#pragma unroll
        for (int o = 16; o > 0; o >>= 1) sum += __shfl_xor_sync(~0u, sum, o);
        float mu = sum * (1.0f / 512.0f);
        float vs = 0.f;
#pragma unroll
        for (int j = 0; j < 16; j++) {
            float d = tile[tr][lane + 32 * j] - mu;
            vs += d * d;
        }
#pragma unroll
        for (int o = 16; o > 0; o >>= 1) vs += __shfl_xor_sync(~0u, vs, o);
        if (lane == 0) {
            smu[tr] = mu;
            srs[tr] = rsqrtf(vs * (1.0f / 512.0f) + 1e-5f);
        }
    }
    __syncthreads();

    for (int idx = t; idx < 16 * 512; idx += 256) {
        int tk = idx >> 9, c = idx & 511;
        float v = (tile[tk][c] - smu[tk]) * srs[tk] * gam[c] + bet[c];
        out[(size_t)(b * ND + n0 + tk) * CD + c] = v;
    }
}

// ---------------------------------------------------------------------------
// TF32 tensor GEMM via mma.sync (sm80-style, compute_103-safe):
//   C[M,512] = A[M,512] @ W^T + bias (+rope / +resid)
// CTA tile 128x128, BK=32, double-buffered smem (pad stride 36 floats:
// conflict-free STS.128 and ldmatrix). 8 warps, warp tile 64x32
// (4x4 mma tiles of m16n8k8). MODE: 0=bias, 1=bias+rope, 2=bias+resid.
// Grid (M/128, 512/128). Dyn smem = 2 stages * 2 tiles * 128*36*4 = 73728 B.
// ---------------------------------------------------------------------------
#define GPAD 36
#define GEMM_DSMEM (2 * 2 * 128 * GPAD * 4)

template <int MODE>
__global__ __launch_bounds__(256) void gemm_mma(const float* __restrict__ A,
                                                const float* __restrict__ W,
                                                const float* __restrict__ bias,
                                                const float* __restrict__ resid,
                                                float* __restrict__ Cout) {
    extern __shared__ float sm[];
    const int t  = threadIdx.x;
    const int m0 = blockIdx.x * 128;
    const int n0 = blockIdx.y * 128;

    uint32_t sb = smem_u32(sm);
    const uint32_t TILE = 128 * GPAD * 4;           // 18432 B
    uint32_t ab[2] = { sb,            sb + 2 * TILE };
    uint32_t bb[2] = { sb + TILE,     sb + 3 * TILE };

    const float4* A4 = (const float4*)(A + (size_t)m0 * 512);
    const float4* B4 = (const float4*)(W + (size_t)n0 * 512);

    float4 ra[4], rb[4];

    auto ldg = [&](int kc) {
#pragma unroll
        for (int j = 0; j < 4; j++) {
            int f = t + j * 256;                    // 0..1023
            ra[j] = A4[(size_t)(f >> 3) * 128 + kc * 8 + (f & 7)];
            rb[j] = B4[(size_t)(f >> 3) * 128 + kc * 8 + (f & 7)];
        }
    };
    auto sts = [&](uint32_t a_, uint32_t b_) {
#pragma unroll
        for (int j = 0; j < 4; j++) {
            int f = t + j * 256;
            uint32_t off = (uint32_t)(f >> 3) * (GPAD * 4) + (uint32_t)(f & 7) * 16;
            sts128(a_ + off, f2tf32(ra[j].x), f2tf32(ra[j].y),
                             f2tf32(ra[j].z), f2tf32(ra[j].w));
            sts128(b_ + off, f2tf32(rb[j].x), f2tf32(rb[j].y),
                             f2tf32(rb[j].z), f2tf32(rb[j].w));
        }
    };

    const int w = t >> 5, lane = t & 31;
    const int wm = (w & 1) * 64;                    // warp M offset
    const int wn = (w >> 1) * 32;                   // warp N offset
    const int q8 = lane >> 3, r8 = lane & 7;

    // ldmatrix per-thread row addresses (byte offsets into a tile)
    // A x4: matrices = [rows, rows+8] x [k, k+4]
    uint32_t aoff = (uint32_t)((wm + ((q8 & 1) << 3) + r8) * GPAD + ((q8 >> 1) << 2)) * 4;
    // B x4: matrices = [n, n+4k? ] -> [k, k+4] x [rows, rows+8]
    uint32_t boff = (uint32_t)((wn + ((q8 >> 1) << 3) + r8) * GPAD + ((q8 & 1) << 2)) * 4;

    float d[4][4][4];
#pragma unroll
    for (int i = 0; i < 4; i++)
#pragma unroll
        for (int j = 0; j < 4; j++)
#pragma unroll
            for (int k = 0; k < 4; k++) d[i][j][k] = 0.f;

    ldg(0);
    sts(ab[0], bb[0]);
    ldg(1);
    __syncthreads();

#pragma unroll 1
    for (int c = 0; c < 16; c++) {
        if (c + 1 < 16) sts(ab[(c + 1) & 1], bb[(c + 1) & 1]);
        if (c + 2 < 16) ldg(c + 2);

        uint32_t abase = ab[c & 1] + aoff;
        uint32_t bbase = bb[c & 1] + boff;
#pragma unroll
        for (int ks = 0; ks < 4; ks++) {
            uint32_t af[4][4], bf[2][4];
#pragma unroll
            for (int mt = 0; mt < 4; mt++)
                ldsm4(af[mt], abase + mt * (16 * GPAD * 4) + ks * 32);
#pragma unroll
            for (int np = 0; np < 2; np++)
                ldsm4(bf[np], bbase + np * (16 * GPAD * 4) + ks * 32);
#pragma unroll
            for (int mt = 0; mt < 4; mt++)
#pragma unroll
                for (int nt = 0; nt < 4; nt++)
                    mma_tf32(d[mt][nt], af[mt], &bf[nt >> 1][(nt & 1) * 2]);
        }
        __syncthreads();
    }

    // Epilogue: c0/c1 = (row, col..col+1), c2/c3 = (row+8, col..col+1)
    const int gr = lane >> 2, gc = lane & 3;
#pragma unroll
    for (int mt = 0; mt < 4; mt++) {
        int row0 = m0 + wm + mt * 16 + gr;
#pragma unroll
        for (int half = 0; half < 2; half++) {
            int row = row0 + half * 8;
            float* crow = Cout + (size_t)row * 512;
            int pos = row & (ND - 1);
#pragma unroll
            for (int nt = 0; nt < 4; nt++) {
                int col = n0 + wn + nt * 8 + gc * 2;
                float2 b2 = *(const float2*)&bias[col];
                float x0 = d[mt][nt][half * 2 + 0] + b2.x;
                float x1 = d[mt][nt][half * 2 + 1] + b2.y;
                float2 o;
                if (MODE == 1) {
                    float2 sc = g_rope[pos * 32 + ((col & 63) >> 1)];
                    o.x = x0 * sc.y - x1 * sc.x;
                    o.y = x0 * sc.x + x1 * sc.y;
                } else if (MODE == 2) {
                    float2 rr = *(const float2*)&resid[(size_t)row * 512 + col];
                    o.x = x0 + rr.x;
                    o.y = x1 + rr.y;
                } else {
                    o.x = x0;
                    o.y = x1;
                }
                *(float2*)&crow[col] = o;
            }
        }
    }
}

// ---------------------------------------------------------------------------
// Windowed attention. grid (64 windows, NH, B), 256 threads.
// ---------------------------------------------------------------------------
__global__ __launch_bounds__(256) void attn_kernel() {
    extern __shared__ float smf[];
    float* Qs = smf;
    float* Ks = smf + 64 * 68;
    float* Vs = smf + 2 * 64 * 68;

    int w = blockIdx.x, h = blockIdx.y, b = blockIdx.z;
    int wy = w >> 3, wx = w & 7;
    size_t base = (size_t)b * ND * CD + (size_t)h * 64;
    const float* Qg = g_Qp + base;
    const float* Kg = g_Kp + base;
    const float* Vg = g_Vp + base;

    int t = threadIdx.x;
#pragma unroll
    for (int it = 0; it < 4; it++) {
        int idx = t + it * 256;
        int r = idx >> 4, c4 = idx & 15;
        int n = (wy * 8 + (r >> 3)) * 64 + wx * 8 + (r & 7);
        size_t ga = (size_t)n * CD + c4 * 4;
        *(float4*)&Qs[r * 68 + c4 * 4] = *(const float4*)&Qg[ga];
        *(float4*)&Ks[r * 68 + c4 * 4] = *(const float4*)&Kg[ga];
        *(float4*)&Vs[r * 68 + c4 * 4] = *(const float4*)&Vg[ga];
    }
    __syncthreads();

    int q = t >> 2, j = t & 3;
    float s[16];
#pragma unroll
    for (int i = 0; i < 16; i++) s[i] = 0.f;

#pragma unroll
    for (int ch = 0; ch < 4; ch++) {
        float4 qv[4];
#pragma unroll
        for (int c = 0; c < 4; c++)
            qv[c] = *(float4*)&Qs[q * 68 + ch * 16 + c * 4];
#pragma unroll
        for (int i = 0; i < 16; i++) {
            int k = i * 4 + j;
            const float* kr = &Ks[k * 68 + ch * 16];
            float4 k0 = *(float4*)&kr[0];
            float4 k1 = *(float4*)&kr[4];
            float4 k2 = *(float4*)&kr[8];
            float4 k3 = *(float4*)&kr[12];
            s[i] += qv[0].x * k0.x + qv[0].y * k0.y + qv[0].z * k0.z + qv[0].w * k0.w
                  + qv[1].x * k1.x + qv[1].y * k1.y + qv[1].z * k1.z + qv[1].w * k1.w
                  + qv[2].x * k2.x + qv[2].y * k2.y + qv[2].z * k2.z + qv[2].w * k2.w
                  + qv[3].x * k3.x + qv[3].y * k3.y + qv[3].z * k3.z + qv[3].w * k3.w;
        }
    }

    const float* brow = g_biasM + h * 4096 + q * 64;
    float mx = -1e30f;
#pragma unroll
    for (int i = 0; i < 16; i++) {
        s[i] = s[i] * 0.125f + __ldg(&brow[i * 4 + j]);
        mx = fmaxf(mx, s[i]);
    }
    mx = fmaxf(mx, __shfl_xor_sync(~0u, mx, 1));
    mx = fmaxf(mx, __shfl_xor_sync(~0u, mx, 2));
    float sum = 0.f;
#pragma unroll
    for (int i = 0; i < 16; i++) {
        s[i] = __expf(s[i] - mx);
        sum += s[i];
    }
    sum += __shfl_xor_sync(~0u, sum, 1);
    sum += __shfl_xor_sync(~0u, sum, 2);
    float inv = 1.0f / sum;

    __syncthreads();
#pragma unroll
    for (int i = 0; i < 16; i++)
        Qs[q * 68 + i * 4 + j] = s[i] * inv;
    __syncthreads();

    float4 o[4];
#pragma unroll
    for (int ii = 0; ii < 4; ii++) o[ii] = make_float4(0.f, 0.f, 0.f, 0.f);
#pragma unroll
    for (int k = 0; k < 64; k++) {
        float p = Qs[q * 68 + k];
        const float* vr = &Vs[k * 68];
#pragma unroll
        for (int ii = 0; ii < 4; ii++) {
            float4 v = *(float4*)&vr[ii * 16 + j * 4];
            o[ii].x += p * v.x; o[ii].y += p * v.y;
            o[ii].z += p * v.z; o[ii].w += p * v.w;
        }
    }

    float* Ob = g_attn + base;
    int n = (wy * 8 + (q >> 3)) * 64 + wx * 8 + (q & 7);
#pragma unroll
    for (int ii = 0; ii < 4; ii++)
        *(float4*)&Ob[(size_t)n * CD + ii * 16 + j * 4] = o[ii];
}

// ---------------------------------------------------------------------------
// Final transpose (B, N, C) -> (B, C, N)
// ---------------------------------------------------------------------------
__global__ __launch_bounds__(256) void transpose_kernel(const float* __restrict__ in,
                                                        float* __restrict__ out) {
    __shared__ float tile[32][33];
    int b  = blockIdx.z;
    int n0 = blockIdx.x * 32;
    int c0 = blockIdx.y * 32;
    int tx = threadIdx.x, ty = threadIdx.y;
#pragma unroll
    for (int r = 0; r < 4; r++)
        tile[ty + r * 8][tx] = in[(size_t)(b * ND + n0 + ty + r * 8) * CD + c0 + tx];
    __syncthreads();
#pragma unroll
    for (int r = 0; r < 4; r++)
        out[(size_t)(b * CD + c0 + ty + r * 8) * ND + n0 + tx] = tile[tx][ty + r * 8];
}

// ---------------------------------------------------------------------------
// Launch
// ---------------------------------------------------------------------------
extern "C" void kernel_launch(void* const* d_in, const int* in_sizes, int n_in,
                              void* d_out, int out_size) {
    const float* q       = (const float*)d_in[0];
    const float* kv      = (const float*)d_in[1];
    const float* g_q     = (const float*)d_in[2];
    const float* b_q_ln  = (const float*)d_in[3];
    const float* g_kv    = (const float*)d_in[4];
    const float* b_kv_ln = (const float*)d_in[5];
    const float* Wq      = (const float*)d_in[6];
    const float* bq      = (const float*)d_in[7];
    const float* Wk      = (const float*)d_in[8];
    const float* bk      = (const float*)d_in[9];
    const float* Wv      = (const float*)d_in[10];
    const float* bv      = (const float*)d_in[11];
    const float* Wo      = (const float*)d_in[12];
    const float* bo      = (const float*)d_in[13];
    const float* btab    = (const float*)d_in[14];
    float* out = (float*)d_out;

    float *qn, *kvn, *Qp, *Kp, *Vp, *att, *proj;
    cudaGetSymbolAddress((void**)&qn,   g_qnorm);
    cudaGetSymbolAddress((void**)&kvn,  g_kvnorm);
    cudaGetSymbolAddress((void**)&Qp,   g_Qp);
    cudaGetSymbolAddress((void**)&Kp,   g_Kp);
    cudaGetSymbolAddress((void**)&Vp,   g_Vp);
    cudaGetSymbolAddress((void**)&att,  g_attn);
    cudaGetSymbolAddress((void**)&proj, g_proj);

    // 1. precompute rope cache + bias matrix
    precompute_kernel<<<512, 256>>>(btab);

    // 2. LayerNorm q, kv
    ln_kernel<<<2048, 256>>>(q,  g_q,  b_q_ln,  qn);
    ln_kernel<<<2048, 256>>>(kv, g_kv, b_kv_ln, kvn);

    // 3. QKV projections on tensor cores (rope fused into Q/K epilogues)
    cudaFuncSetAttribute(gemm_mma<0>, cudaFuncAttributeMaxDynamicSharedMemorySize, GEMM_DSMEM);
    cudaFuncSetAttribute(gemm_mma<1>, cudaFuncAttributeMaxDynamicSharedMemorySize, GEMM_DSMEM);
    cudaFuncSetAttribute(gemm_mma<2>, cudaFuncAttributeMaxDynamicSharedMemorySize, GEMM_DSMEM);

    dim3 ggrid(NTOK / 128, 4);
    gemm_mma<1><<<ggrid, 256, GEMM_DSMEM>>>(qn,  Wq, bq, nullptr, Qp);
    gemm_mma<1><<<ggrid, 256, GEMM_DSMEM>>>(kvn, Wk, bk, nullptr, Kp);
    gemm_mma<0><<<ggrid, 256, GEMM_DSMEM>>>(kvn, Wv, bv, nullptr, Vp);

    // 4. windowed attention
    int smem = 3 * 64 * 68 * (int)sizeof(float);
    cudaFuncSetAttribute(attn_kernel, cudaFuncAttributeMaxDynamicSharedMemorySize, smem);
    attn_kernel<<<dim3(64, NHD, BD), 256, smem>>>();

    // 5. output projection + residual with normed q
    gemm_mma<2><<<ggrid, 256, GEMM_DSMEM>>>(att, Wo, bo, qn, proj);

    // 6. (B,N,C) -> (B,C,H,W)
    transpose_kernel<<<dim3(ND / 32, CD / 32, BD), dim3(32, 8)>>>(proj, out);
}

// round 16
// speedup vs baseline: 2.3870x; 1.3108x over previous
#include <cuda_runtime.h>
#include <cuda_bf16.h>
#include <math.h>
#include <stdint.h>

// ---------------------------------------------------------------------------
// Problem constants
// ---------------------------------------------------------------------------
#define BD   8
#define CD   512
#define ND   4096          // H*W tokens per batch
#define NHD  8
#define DDIM 64
#define NTOK (BD * ND)     // 32768

// ---------------------------------------------------------------------------
// Scratch: __device__ globals (allocation-free)
// ---------------------------------------------------------------------------
__device__ float  g_qnorm [NTOK * CD];   // (B*N, C) LN'ed q
__device__ float  g_kvnorm[NTOK * CD];   // (B*N, C) LN'ed kv
__device__ float  g_Qp    [NTOK * CD];   // projected Q (rope fused in epilogue)
__device__ float  g_Kp    [NTOK * CD];
__device__ float  g_Vp    [NTOK * CD];
__device__ float  g_attn  [NTOK * CD];   // attention output (B*N, C)
__device__ float2 g_rope  [ND * 32];     // (pos, i) -> (sin, cos)
__device__ float  g_biasM [NHD * 64 * 64]; // (h, q, k) expanded rel-pos bias

// ---------------------------------------------------------------------------
// PTX helpers (compute_103-safe: sm_80 era tensor ops only)
// ---------------------------------------------------------------------------
__device__ __forceinline__ uint32_t smem_u32(const void* p) {
    uint32_t a;
    asm("{ .reg .u64 t; cvta.to.shared.u64 t, %1; cvt.u32.u64 %0, t; }"
        : "=r"(a) : "l"(p));
    return a;
}

__device__ __forceinline__ uint32_t f2tf32(float x) {
    uint32_t r;
    asm("cvt.rna.tf32.f32 %0, %1;" : "=r"(r) : "f"(x));
    return r;
}

__device__ __forceinline__ float4 cvt4(float4 v) {
    return make_float4(__uint_as_float(f2tf32(v.x)), __uint_as_float(f2tf32(v.y)),
                       __uint_as_float(f2tf32(v.z)), __uint_as_float(f2tf32(v.w)));
}

__device__ __forceinline__ void sts128(uint32_t addr, uint32_t a, uint32_t b,
                                       uint32_t c, uint32_t d) {
    asm volatile("st.shared.v4.b32 [%0], {%1,%2,%3,%4};"
                 :: "r"(addr), "r"(a), "r"(b), "r"(c), "r"(d) : "memory");
}

__device__ __forceinline__ void ldsm4(uint32_t* r, uint32_t addr) {
    asm volatile("ldmatrix.sync.aligned.m8n8.x4.shared.b16 {%0,%1,%2,%3}, [%4];"
                 : "=r"(r[0]), "=r"(r[1]), "=r"(r[2]), "=r"(r[3]) : "r"(addr));
}

__device__ __forceinline__ void mma_tf32(float* d, const uint32_t* a, const uint32_t* b) {
    asm volatile(
        "mma.sync.aligned.m16n8k8.row.col.f32.tf32.tf32.f32 "
        "{%0,%1,%2,%3}, {%4,%5,%6,%7}, {%8,%9}, {%0,%1,%2,%3};"
        : "+f"(d[0]), "+f"(d[1]), "+f"(d[2]), "+f"(d[3])
        : "r"(a[0]), "r"(a[1]), "r"(a[2]), "r"(a[3]), "r"(b[0]), "r"(b[1]));
}

// ---------------------------------------------------------------------------
// Precompute: RoPE cache + expanded bias matrix
// ---------------------------------------------------------------------------
__global__ __launch_bounds__(256) void precompute_kernel(const float* __restrict__ bt) {
    __shared__ float invf[32];
    if (threadIdx.x < 32)
        invf[threadIdx.x] = (float)(1.0 / pow(10000.0, (double)threadIdx.x / 32.0));
    __syncthreads();

    int t = blockIdx.x * 256 + threadIdx.x;
    {
        int pos = t >> 5, i = t & 31;
        float ang = (float)pos * invf[i];
        g_rope[t] = make_float2(sinf(ang), cosf(ang));
    }
    if (t < NHD * 64 * 64) {
        int h = t >> 12, q = (t >> 6) & 63, k = t & 63;
        int dr = (q >> 3) - (k >> 3) + 7;
        int dc = (q & 7) - (k & 7) + 7;
        g_biasM[t] = bt[(dr * 15 + dc) * NHD + h];
    }
}

// ---------------------------------------------------------------------------
// LayerNorm over C per token; NCHW (B,C,N) -> token-major (B*N, C)
// ---------------------------------------------------------------------------
__global__ __launch_bounds__(256) void ln_kernel(const float* __restrict__ x,
                                                 const float* __restrict__ gam,
                                                 const float* __restrict__ bet,
                                                 float* __restrict__ out) {
    __shared__ float tile[16][513];
    __shared__ float smu[16], srs[16];

    int blk = blockIdx.x;
    int b   = blk >> 8;
    int n0  = (blk & 255) << 4;
    const float* xb = x + (size_t)b * CD * ND;
    int t = threadIdx.x;
    int tok = t & 15, cb = t >> 4;

#pragma unroll
    for (int k = 0; k < 32; k++) {
        int c = cb + (k << 4);
        tile[tok][c] = xb[(size_t)c * ND + n0 + tok];
    }
    __syncthreads();

    int lane = t & 31, w = t >> 5;
#pragma unroll
    for (int s = 0; s < 2; s++) {
        int tr = w * 2 + s;
        float sum = 0.f;
#pragma unroll
        for (int j = 0; j < 16; j++) sum += tile[tr][lane + 32 * j];
#pragma unroll
        for (int o = 16; o > 0; o >>= 1) sum += __shfl_xor_sync(~0u, sum, o);
        float mu = sum * (1.0f / 512.0f);
        float vs = 0.f;
#pragma unroll
        for (int j = 0; j < 16; j++) {
            float d = tile[tr][lane + 32 * j] - mu;
            vs += d * d;
        }
#pragma unroll
        for (int o = 16; o > 0; o >>= 1) vs += __shfl_xor_sync(~0u, vs, o);
        if (lane == 0) {
            smu[tr] = mu;
            srs[tr] = rsqrtf(vs * (1.0f / 512.0f) + 1e-5f);
        }
    }
    __syncthreads();

    for (int idx = t; idx < 16 * 512; idx += 256) {
        int tk = idx >> 9, c = idx & 511;
        float v = (tile[tk][c] - smu[tk]) * srs[tk] * gam[c] + bet[c];
        out[(size_t)(b * ND + n0 + tk) * CD + c] = v;
    }
}

// ---------------------------------------------------------------------------
// TF32 tensor GEMM via mma.sync:
//   C[M,512] = A[M,512] @ W^T + bias (+rope / +resid)
// CTA tile 128x128, BK=32, double-buffered smem, 8 warps, warp tile 64x32.
// MODE: 0=bias, 1=bias+rope, 2=bias+resid with transposed write to (B,C,N).
// ---------------------------------------------------------------------------
#define GPAD 36
#define GEMM_DSMEM (2 * 2 * 128 * GPAD * 4)

template <int MODE>
__global__ __launch_bounds__(256) void gemm_mma(const float* __restrict__ A,
                                                const float* __restrict__ W,
                                                const float* __restrict__ bias,
                                                const float* __restrict__ resid,
                                                float* __restrict__ Cout) {
    extern __shared__ float sm[];
    const int t  = threadIdx.x;
    const int m0 = blockIdx.x * 128;
    const int n0 = blockIdx.y * 128;

    uint32_t sb = smem_u32(sm);
    const uint32_t TILE = 128 * GPAD * 4;           // 18432 B
    uint32_t ab[2] = { sb,            sb + 2 * TILE };
    uint32_t bb[2] = { sb + TILE,     sb + 3 * TILE };

    const float4* A4 = (const float4*)(A + (size_t)m0 * 512);
    const float4* B4 = (const float4*)(W + (size_t)n0 * 512);

    float4 ra[4], rb[4];

    auto ldg = [&](int kc) {
#pragma unroll
        for (int j = 0; j < 4; j++) {
            int f = t + j * 256;                    // 0..1023
            ra[j] = A4[(size_t)(f >> 3) * 128 + kc * 8 + (f & 7)];
            rb[j] = B4[(size_t)(f >> 3) * 128 + kc * 8 + (f & 7)];
        }
    };
    auto sts = [&](uint32_t a_, uint32_t b_) {
#pragma unroll
        for (int j = 0; j < 4; j++) {
            int f = t + j * 256;
            uint32_t off = (uint32_t)(f >> 3) * (GPAD * 4) + (uint32_t)(f & 7) * 16;
            sts128(a_ + off, f2tf32(ra[j].x), f2tf32(ra[j].y),
                             f2tf32(ra[j].z), f2tf32(ra[j].w));
            sts128(b_ + off, f2tf32(rb[j].x), f2tf32(rb[j].y),
                             f2tf32(rb[j].z), f2tf32(rb[j].w));
        }
    };

    const int w = t >> 5, lane = t & 31;
    const int wm = (w & 1) * 64;                    // warp M offset
    const int wn = (w >> 1) * 32;                   // warp N offset
    const int q8 = lane >> 3, r8 = lane & 7;

    uint32_t aoff = (uint32_t)((wm + ((q8 & 1) << 3) + r8) * GPAD + ((q8 >> 1) << 2)) * 4;
    uint32_t boff = (uint32_t)((wn + ((q8 >> 1) << 3) + r8) * GPAD + ((q8 & 1) << 2)) * 4;

    float d[4][4][4];
#pragma unroll
    for (int i = 0; i < 4; i++)
#pragma unroll
        for (int j = 0; j < 4; j++)
#pragma unroll
            for (int k = 0; k < 4; k++) d[i][j][k] = 0.f;

    ldg(0);
    sts(ab[0], bb[0]);
    ldg(1);
    __syncthreads();

#pragma unroll 1
    for (int c = 0; c < 16; c++) {
        if (c + 1 < 16) sts(ab[(c + 1) & 1], bb[(c + 1) & 1]);
        if (c + 2 < 16) ldg(c + 2);

        uint32_t abase = ab[c & 1] + aoff;
        uint32_t bbase = bb[c & 1] + boff;
#pragma unroll
        for (int ks = 0; ks < 4; ks++) {
            uint32_t af[4][4], bf[2][4];
#pragma unroll
            for (int mt = 0; mt < 4; mt++)
                ldsm4(af[mt], abase + mt * (16 * GPAD * 4) + ks * 32);
#pragma unroll
            for (int np = 0; np < 2; np++)
                ldsm4(bf[np], bbase + np * (16 * GPAD * 4) + ks * 32);
#pragma unroll
            for (int mt = 0; mt < 4; mt++)
#pragma unroll
                for (int nt = 0; nt < 4; nt++)
                    mma_tf32(d[mt][nt], af[mt], &bf[nt >> 1][(nt & 1) * 2]);
        }
        __syncthreads();
    }

    const int gr = lane >> 2, gc = lane & 3;

    if (MODE == 2) {
        // Stage output tile transposed in smem (bias+resid fused), then write
        // directly to d_out in (B, C, N) layout, fully coalesced.
        float* stile = sm;   // 128 x 132 floats = 67584 B (fits in GEMM_DSMEM)
#pragma unroll
        for (int mt = 0; mt < 4; mt++) {
#pragma unroll
            for (int half = 0; half < 2; half++) {
                int row = wm + mt * 16 + gr + half * 8;       // local row (n dim)
                int grow = m0 + row;
#pragma unroll
                for (int nt = 0; nt < 4; nt++) {
                    int col = wn + nt * 8 + gc * 2;           // local col (C dim)
                    float2 b2 = *(const float2*)&bias[n0 + col];
                    float2 rr = *(const float2*)&resid[(size_t)grow * 512 + n0 + col];
                    stile[(col + 0) * 132 + row] = d[mt][nt][half * 2 + 0] + b2.x + rr.x;
                    stile[(col + 1) * 132 + row] = d[mt][nt][half * 2 + 1] + b2.y + rr.y;
                }
            }
        }
        __syncthreads();
        int b   = m0 >> 12;
        int nb0 = m0 & 4095;
#pragma unroll
        for (int cc = 0; cc < 16; cc++) {
            int col = w * 16 + cc;
            float4 v = *(float4*)&stile[col * 132 + lane * 4];
            *(float4*)&Cout[((size_t)(b * 512) + n0 + col) * 4096 + nb0 + lane * 4] = v;
        }
    } else {
#pragma unroll
        for (int mt = 0; mt < 4; mt++) {
            int row0 = m0 + wm + mt * 16 + gr;
#pragma unroll
            for (int half = 0; half < 2; half++) {
                int row = row0 + half * 8;
                float* crow = Cout + (size_t)row * 512;
                int pos = row & (ND - 1);
#pragma unroll
                for (int nt = 0; nt < 4; nt++) {
                    int col = n0 + wn + nt * 8 + gc * 2;
                    float2 b2 = *(const float2*)&bias[col];
                    float x0 = d[mt][nt][half * 2 + 0] + b2.x;
                    float x1 = d[mt][nt][half * 2 + 1] + b2.y;
                    float2 o;
                    if (MODE == 1) {
                        float2 sc = g_rope[pos * 32 + ((col & 63) >> 1)];
                        o.x = x0 * sc.y - x1 * sc.x;
                        o.y = x0 * sc.x + x1 * sc.y;
                    } else {
                        o.x = x0;
                        o.y = x1;
                    }
                    *(float2*)&crow[col] = o;
                }
            }
        }
    }
}

// ---------------------------------------------------------------------------
// Windowed attention on tensor cores (TF32 mma.sync).
// grid (64 windows, NH, B), 128 threads (4 warps). One (b,h,window) per CTA.
// Warp tile m16 x n64; S and O both via m16n8k8; softmax via quad shfl.
// Dyn smem: Q[64x68], K[64x68], V^T[64x68], P[64x68] = 69632 B.
// Row stride 68*4 = 272 B (16B multiple -> ldmatrix-legal; 68 mod 32 = 4 ->
// 8 consecutive rows hit distinct 4-bank groups, conflict-free).
// ---------------------------------------------------------------------------
#define APAD 68
#define ATTN_DSMEM (4 * 64 * APAD * 4)

__global__ __launch_bounds__(128) void attn_kernel() {
    extern __shared__ float smd[];
    float* qs  = smd;
    float* ksm = smd + 64 * APAD;
    float* vt  = smd + 2 * 64 * APAD;
    float* ps  = smd + 3 * 64 * APAD;

    int w = blockIdx.x, h = blockIdx.y, b = blockIdx.z;
    int wy = w >> 3, wx = w & 7;
    size_t base = (size_t)b * ND * CD + (size_t)h * 64;
    const float* Qg = g_Qp + base;
    const float* Kg = g_Kp + base;
    const float* Vg = g_Vp + base;

    int t = threadIdx.x;
#pragma unroll
    for (int it = 0; it < 8; it++) {
        int idx = t + it * 128;
        int r = idx >> 4, c4 = idx & 15;               // r = row (q/key), c4 = d/4
        int n = (wy * 8 + (r >> 3)) * 64 + wx * 8 + (r & 7);
        size_t ga = (size_t)n * CD + c4 * 4;
        *(float4*)&qs [r * APAD + c4 * 4] = cvt4(*(const float4*)&Qg[ga]);
        *(float4*)&ksm[r * APAD + c4 * 4] = cvt4(*(const float4*)&Kg[ga]);
        float4 vv = cvt4(*(const float4*)&Vg[ga]);
        vt[(c4 * 4 + 0) * APAD + r] = vv.x;            // transposed: [d][key]
        vt[(c4 * 4 + 1) * APAD + r] = vv.y;
        vt[(c4 * 4 + 2) * APAD + r] = vv.z;
        vt[(c4 * 4 + 3) * APAD + r] = vv.w;
    }
    __syncthreads();

    const int wid = t >> 5, lane = t & 31;
    const int q8 = lane >> 3, r8 = lane & 7;
    uint32_t qsb = smem_u32(qs), ksb = smem_u32(ksm);
    uint32_t vtb = smem_u32(vt), psb = smem_u32(ps);

    uint32_t aoff = (uint32_t)((wid * 16 + ((q8 & 1) << 3) + r8) * APAD + ((q8 >> 1) << 2)) * 4;
    uint32_t boff[4];
#pragma unroll
    for (int np = 0; np < 4; np++)
        boff[np] = (uint32_t)((np * 16 + ((q8 >> 1) << 3) + r8) * APAD + ((q8 & 1) << 2)) * 4;

    // ---- S = Q @ K^T ----
    float s[8][4];
#pragma unroll
    for (int i = 0; i < 8; i++)
#pragma unroll
        for (int j = 0; j < 4; j++) s[i][j] = 0.f;

#pragma unroll
    for (int kc = 0; kc < 8; kc++) {
        uint32_t af[4], bf[4][4];
        ldsm4(af, qsb + aoff + kc * 32);
#pragma unroll
        for (int np = 0; np < 4; np++)
            ldsm4(bf[np], ksb + boff[np] + kc * 32);
#pragma unroll
        for (int nt = 0; nt < 8; nt++)
            mma_tf32(s[nt], af, &bf[nt >> 1][(nt & 1) * 2]);
    }

    // ---- scale + bias + softmax (rows q0 = wid*16+gr, q1 = q0+8) ----
    const int gr = lane >> 2, gc = lane & 3;
    const int q0 = wid * 16 + gr, q1 = q0 + 8;
    const float* br0 = g_biasM + h * 4096 + q0 * 64;
    const float* br1 = g_biasM + h * 4096 + q1 * 64;

    float mx0 = -1e30f, mx1 = -1e30f;
#pragma unroll
    for (int nt = 0; nt < 8; nt++) {
        int col = nt * 8 + gc * 2;
        float2 b0 = *(const float2*)&br0[col];
        float2 b1 = *(const float2*)&br1[col];
        s[nt][0] = s[nt][0] * 0.125f + b0.x;
        s[nt][1] = s[nt][1] * 0.125f + b0.y;
        s[nt][2] = s[nt][2] * 0.125f + b1.x;
        s[nt][3] = s[nt][3] * 0.125f + b1.y;
        mx0 = fmaxf(mx0, fmaxf(s[nt][0], s[nt][1]));
        mx1 = fmaxf(mx1, fmaxf(s[nt][2], s[nt][3]));
    }
    mx0 = fmaxf(mx0, __shfl_xor_sync(~0u, mx0, 1));
    mx0 = fmaxf(mx0, __shfl_xor_sync(~0u, mx0, 2));
    mx1 = fmaxf(mx1, __shfl_xor_sync(~0u, mx1, 1));
    mx1 = fmaxf(mx1, __shfl_xor_sync(~0u, mx1, 2));

    float sum0 = 0.f, sum1 = 0.f;
#pragma unroll
    for (int nt = 0; nt < 8; nt++) {
        s[nt][0] = __expf(s[nt][0] - mx0);
        s[nt][1] = __expf(s[nt][1] - mx0);
        s[nt][2] = __expf(s[nt][2] - mx1);
        s[nt][3] = __expf(s[nt][3] - mx1);
        sum0 += s[nt][0] + s[nt][1];
        sum1 += s[nt][2] + s[nt][3];
    }
    sum0 += __shfl_xor_sync(~0u, sum0, 1);
    sum0 += __shfl_xor_sync(~0u, sum0, 2);
    sum1 += __shfl_xor_sync(~0u, sum1, 1);
    sum1 += __shfl_xor_sync(~0u, sum1, 2);
    float inv0 = 1.0f / sum0, inv1 = 1.0f / sum1;

    // store P row-major (tf32-rounded); P rows are warp-local
#pragma unroll
    for (int nt = 0; nt < 8; nt++) {
        int col = nt * 8 + gc * 2;
        float2 p0 = make_float2(__uint_as_float(f2tf32(s[nt][0] * inv0)),
                                __uint_as_float(f2tf32(s[nt][1] * inv0)));
        float2 p1 = make_float2(__uint_as_float(f2tf32(s[nt][2] * inv1)),
                                __uint_as_float(f2tf32(s[nt][3] * inv1)));
        *(float2*)&ps[q0 * APAD + col] = p0;
        *(float2*)&ps[q1 * APAD + col] = p1;
    }
    __syncwarp();

    // ---- O = P @ V  (B = V^T stored [d][key]) ----
    float o[8][4];
#pragma unroll
    for (int i = 0; i < 8; i++)
#pragma unroll
        for (int j = 0; j < 4; j++) o[i][j] = 0.f;

#pragma unroll
    for (int kc = 0; kc < 8; kc++) {
        uint32_t af[4], bf[4][4];
        ldsm4(af, psb + aoff + kc * 32);
#pragma unroll
        for (int np = 0; np < 4; np++)
            ldsm4(bf[np], vtb + boff[np] + kc * 32);
#pragma unroll
        for (int nt = 0; nt < 8; nt++)
            mma_tf32(o[nt], af, &bf[nt >> 1][(nt & 1) * 2]);
    }

    // ---- write O ----
    float* Ob = g_attn + base;
    int n0t = (wy * 8 + (q0 >> 3)) * 64 + wx * 8 + (q0 & 7);
    int n1t = (wy * 8 + (q1 >> 3)) * 64 + wx * 8 + (q1 & 7);
#pragma unroll
    for (int nt = 0; nt < 8; nt++) {
        int col = nt * 8 + gc * 2;
        *(float2*)&Ob[(size_t)n0t * CD + col] = make_float2(o[nt][0], o[nt][1]);
        *(float2*)&Ob[(size_t)n1t * CD + col] = make_float2(o[nt][2], o[nt][3]);
    }
}

// ---------------------------------------------------------------------------
// Launch
// ---------------------------------------------------------------------------
extern "C" void kernel_launch(void* const* d_in, const int* in_sizes, int n_in,
                              void* d_out, int out_size) {
    const float* q       = (const float*)d_in[0];
    const float* kv      = (const float*)d_in[1];
    const float* g_q     = (const float*)d_in[2];
    const float* b_q_ln  = (const float*)d_in[3];
    const float* g_kv    = (const float*)d_in[4];
    const float* b_kv_ln = (const float*)d_in[5];
    const float* Wq      = (const float*)d_in[6];
    const float* bq      = (const float*)d_in[7];
    const float* Wk      = (const float*)d_in[8];
    const float* bk      = (const float*)d_in[9];
    const float* Wv      = (const float*)d_in[10];
    const float* bv      = (const float*)d_in[11];
    const float* Wo      = (const float*)d_in[12];
    const float* bo      = (const float*)d_in[13];
    const float* btab    = (const float*)d_in[14];
    float* out = (float*)d_out;

    float *qn, *kvn, *Qp, *Kp, *Vp, *att;
    cudaGetSymbolAddress((void**)&qn,  g_qnorm);
    cudaGetSymbolAddress((void**)&kvn, g_kvnorm);
    cudaGetSymbolAddress((void**)&Qp,  g_Qp);
    cudaGetSymbolAddress((void**)&Kp,  g_Kp);
    cudaGetSymbolAddress((void**)&Vp,  g_Vp);
    cudaGetSymbolAddress((void**)&att, g_attn);

    // 1. precompute rope cache + bias matrix
    precompute_kernel<<<512, 256>>>(btab);

    // 2. LayerNorm q, kv
    ln_kernel<<<2048, 256>>>(q,  g_q,  b_q_ln,  qn);
    ln_kernel<<<2048, 256>>>(kv, g_kv, b_kv_ln, kvn);

    // 3. QKV projections on tensor cores (rope fused into Q/K epilogues)
    cudaFuncSetAttribute(gemm_mma<0>, cudaFuncAttributeMaxDynamicSharedMemorySize, GEMM_DSMEM);
    cudaFuncSetAttribute(gemm_mma<1>, cudaFuncAttributeMaxDynamicSharedMemorySize, GEMM_DSMEM);
    cudaFuncSetAttribute(gemm_mma<2>, cudaFuncAttributeMaxDynamicSharedMemorySize, GEMM_DSMEM);

    dim3 ggrid(NTOK / 128, 4);
    gemm_mma<1><<<ggrid, 256, GEMM_DSMEM>>>(qn,  Wq, bq, nullptr, Qp);
    gemm_mma<1><<<ggrid, 256, GEMM_DSMEM>>>(kvn, Wk, bk, nullptr, Kp);
    gemm_mma<0><<<ggrid, 256, GEMM_DSMEM>>>(kvn, Wv, bv, nullptr, Vp);

    // 4. windowed attention on tensor cores
    cudaFuncSetAttribute(attn_kernel, cudaFuncAttributeMaxDynamicSharedMemorySize, ATTN_DSMEM);
    attn_kernel<<<dim3(64, NHD, BD), 128, ATTN_DSMEM>>>();

    // 5. output projection + residual, transposed write straight to (B,C,H,W)
    gemm_mma<2><<<ggrid, 256, GEMM_DSMEM>>>(att, Wo, bo, qn, out);
}

// round 17
// speedup vs baseline: 2.5293x; 1.0596x over previous
#include <cuda_runtime.h>
#include <cuda_bf16.h>
#include <math.h>
#include <stdint.h>

// ---------------------------------------------------------------------------
// Problem constants
// ---------------------------------------------------------------------------
#define BD   8
#define CD   512
#define ND   4096          // H*W tokens per batch
#define NHD  8
#define DDIM 64
#define NTOK (BD * ND)     // 32768

// ---------------------------------------------------------------------------
// Scratch: __device__ globals (allocation-free)
// ---------------------------------------------------------------------------
__device__ float  g_qnorm [NTOK * CD];   // LN'ed q, tf32-rounded (also residual)
__device__ float  g_kvnorm[NTOK * CD];   // LN'ed kv, tf32-rounded
__device__ float  g_Qp    [NTOK * CD];   // projected Q (rope fused in epilogue)
__device__ float  g_Kp    [NTOK * CD];
__device__ float  g_Vp    [NTOK * CD];
__device__ float  g_attn  [NTOK * CD];   // attention output, tf32-rounded
__device__ float  g_Wr    [4][CD * CD];  // tf32-rounded weights (q,k,v,o)
__device__ float2 g_rope  [ND * 32];     // (pos, i) -> (sin, cos)
__device__ float  g_biasM [NHD * 64 * 64]; // (h, q, k) expanded rel-pos bias

// ---------------------------------------------------------------------------
// PTX helpers (compute_103-safe: sm_80 era ops only)
// ---------------------------------------------------------------------------
__device__ __forceinline__ uint32_t smem_u32(const void* p) {
    uint32_t a;
    asm("{ .reg .u64 t; cvta.to.shared.u64 t, %1; cvt.u32.u64 %0, t; }"
        : "=r"(a) : "l"(p));
    return a;
}

__device__ __forceinline__ uint32_t f2tf32(float x) {
    uint32_t r;
    asm("cvt.rna.tf32.f32 %0, %1;" : "=r"(r) : "f"(x));
    return r;
}
__device__ __forceinline__ float rtf(float x) { return __uint_as_float(f2tf32(x)); }

__device__ __forceinline__ float4 cvt4(float4 v) {
    return make_float4(rtf(v.x), rtf(v.y), rtf(v.z), rtf(v.w));
}

__device__ __forceinline__ void cpasync16(uint32_t s, const void* g) {
    asm volatile("cp.async.cg.shared.global [%0], [%1], 16;"
                 :: "r"(s), "l"(g) : "memory");
}

__device__ __forceinline__ void ldsm4(uint32_t* r, uint32_t addr) {
    asm volatile("ldmatrix.sync.aligned.m8n8.x4.shared.b16 {%0,%1,%2,%3}, [%4];"
                 : "=r"(r[0]), "=r"(r[1]), "=r"(r[2]), "=r"(r[3]) : "r"(addr));
}

__device__ __forceinline__ void mma_tf32(float* d, const uint32_t* a, const uint32_t* b) {
    asm volatile(
        "mma.sync.aligned.m16n8k8.row.col.f32.tf32.tf32.f32 "
        "{%0,%1,%2,%3}, {%4,%5,%6,%7}, {%8,%9}, {%0,%1,%2,%3};"
        : "+f"(d[0]), "+f"(d[1]), "+f"(d[2]), "+f"(d[3])
        : "r"(a[0]), "r"(a[1]), "r"(a[2]), "r"(a[3]), "r"(b[0]), "r"(b[1]));
}

// ---------------------------------------------------------------------------
// Precompute: RoPE cache + expanded bias matrix
// ---------------------------------------------------------------------------
__global__ __launch_bounds__(256) void precompute_kernel(const float* __restrict__ bt) {
    __shared__ float invf[32];
    if (threadIdx.x < 32)
        invf[threadIdx.x] = (float)(1.0 / pow(10000.0, (double)threadIdx.x / 32.0));
    __syncthreads();

    int t = blockIdx.x * 256 + threadIdx.x;
    {
        int pos = t >> 5, i = t & 31;
        float ang = (float)pos * invf[i];
        g_rope[t] = make_float2(sinf(ang), cosf(ang));
    }
    if (t < NHD * 64 * 64) {
        int h = t >> 12, q = (t >> 6) & 63, k = t & 63;
        int dr = (q >> 3) - (k >> 3) + 7;
        int dc = (q & 7) - (k & 7) + 7;
        g_biasM[t] = bt[(dr * 15 + dc) * NHD + h];
    }
}

// ---------------------------------------------------------------------------
// Pre-round all four weight matrices to tf32 (once; enables raw cp.async)
// grid 1024 x 256 -> t in [0, 262144)
// ---------------------------------------------------------------------------
__global__ __launch_bounds__(256) void roundw_kernel(const float* __restrict__ wq,
                                                     const float* __restrict__ wk,
                                                     const float* __restrict__ wv,
                                                     const float* __restrict__ wo) {
    int t = blockIdx.x * 256 + threadIdx.x;
    g_Wr[0][t] = rtf(wq[t]);
    g_Wr[1][t] = rtf(wk[t]);
    g_Wr[2][t] = rtf(wv[t]);
    g_Wr[3][t] = rtf(wo[t]);
}

// ---------------------------------------------------------------------------
// LayerNorm over C per token; NCHW (B,C,N) -> token-major (B*N, C), tf32-rounded
// ---------------------------------------------------------------------------
__global__ __launch_bounds__(256) void ln_kernel(const float* __restrict__ x,
                                                 const float* __restrict__ gam,
                                                 const float* __restrict__ bet,
                                                 float* __restrict__ out) {
    __shared__ float tile[16][513];
    __shared__ float smu[16], srs[16];

    int blk = blockIdx.x;
    int b   = blk >> 8;
    int n0  = (blk & 255) << 4;
    const float* xb = x + (size_t)b * CD * ND;
    int t = threadIdx.x;
    int tok = t & 15, cb = t >> 4;

#pragma unroll
    for (int k = 0; k < 32; k++) {
        int c = cb + (k << 4);
        tile[tok][c] = xb[(size_t)c * ND + n0 + tok];
    }
    __syncthreads();

    int lane = t & 31, w = t >> 5;
#pragma unroll
    for (int s = 0; s < 2; s++) {
        int tr = w * 2 + s;
        float sum = 0.f;
#pragma unroll
        for (int j = 0; j < 16; j++) sum += tile[tr][lane + 32 * j];
#pragma unroll
        for (int o = 16; o > 0; o >>= 1) sum += __shfl_xor_sync(~0u, sum, o);
        float mu = sum * (1.0f / 512.0f);
        float vs = 0.f;
#pragma unroll
        for (int j = 0; j < 16; j++) {
            float d = tile[tr][lane + 32 * j] - mu;
            vs += d * d;
        }
#pragma unroll
        for (int o = 16; o > 0; o >>= 1) vs += __shfl_xor_sync(~0u, vs, o);
        if (lane == 0) {
            smu[tr] = mu;
            srs[tr] = rsqrtf(vs * (1.0f / 512.0f) + 1e-5f);
        }
    }
    __syncthreads();

    for (int idx = t; idx < 16 * 512; idx += 256) {
        int tk = idx >> 9, c = idx & 511;
        float v = (tile[tk][c] - smu[tk]) * srs[tk] * gam[c] + bet[c];
        out[(size_t)(b * ND + n0 + tk) * CD + c] = rtf(v);
    }
}

// ---------------------------------------------------------------------------
// TF32 tensor GEMM v2: cp.async + 64x64 warp tiles.
//   C[M,512] = A[M,512] @ W^T + bias (+rope / +resid)
// CTA tile 128x128, BK=32, 128 threads (4 warps, 2M x 2N), warp tile 64x64.
// A and W are pre-rounded to tf32 -> raw 16B cp.async, no cvt in loop.
// MODE: 0=bias, 1=bias+rope, 2=bias+resid with transposed write to (B,C,N).
// ---------------------------------------------------------------------------
#define GPAD 36
#define GEMM_DSMEM (4 * 128 * GPAD * 4)   // 73728 B

template <int MODE>
__global__ __launch_bounds__(128) void gemm_mma(const float* __restrict__ A,
                                                const float* __restrict__ W,
                                                const float* __restrict__ bias,
                                                const float* __restrict__ resid,
                                                float* __restrict__ Cout) {
    extern __shared__ float sm[];
    const int t  = threadIdx.x;
    const int m0 = blockIdx.x * 128;
    const int n0 = blockIdx.y * 128;

    uint32_t sb = smem_u32(sm);
    const uint32_t TILE = 128 * GPAD * 4;           // 18432 B
    uint32_t ab[2] = { sb,            sb + 2 * TILE };
    uint32_t bb[2] = { sb + TILE,     sb + 3 * TILE };

    const float4* A4 = (const float4*)(A + (size_t)m0 * 512);
    const float4* B4 = (const float4*)(W + (size_t)n0 * 512);

    auto issue = [&](int kc, int buf) {
#pragma unroll
        for (int j = 0; j < 8; j++) {
            int f = t + j * 128;                    // 0..1023
            int row = f >> 3, c4 = f & 7;
            uint32_t off = (uint32_t)row * (GPAD * 4) + (uint32_t)c4 * 16;
            cpasync16(ab[buf] + off, (const void*)(A4 + (size_t)row * 128 + kc * 8 + c4));
            cpasync16(bb[buf] + off, (const void*)(B4 + (size_t)row * 128 + kc * 8 + c4));
        }
        asm volatile("cp.async.commit_group;" ::: "memory");
    };

    const int w = t >> 5, lane = t & 31;
    const int wm = (w & 1) * 64;                    // warp M offset
    const int wn = (w >> 1) * 64;                   // warp N offset
    const int q8 = lane >> 3, r8 = lane & 7;

    uint32_t aoff = (uint32_t)((wm + ((q8 & 1) << 3) + r8) * GPAD + ((q8 >> 1) << 2)) * 4;
    uint32_t boff = (uint32_t)((wn + ((q8 >> 1) << 3) + r8) * GPAD + ((q8 & 1) << 2)) * 4;

    float d[4][8][4];
#pragma unroll
    for (int i = 0; i < 4; i++)
#pragma unroll
        for (int j = 0; j < 8; j++)
#pragma unroll
            for (int k = 0; k < 4; k++) d[i][j][k] = 0.f;

    issue(0, 0);
    issue(1, 1);

#pragma unroll 1
    for (int c = 0; c < 16; c++) {
        if (c < 15) asm volatile("cp.async.wait_group 1;" ::: "memory");
        else        asm volatile("cp.async.wait_group 0;" ::: "memory");
        __syncthreads();

        uint32_t abase = ab[c & 1] + aoff;
        uint32_t bbase = bb[c & 1] + boff;
#pragma unroll
        for (int ks = 0; ks < 4; ks++) {
            uint32_t af[4][4], bf[4][4];
#pragma unroll
            for (int mt = 0; mt < 4; mt++)
                ldsm4(af[mt], abase + mt * (16 * GPAD * 4) + ks * 32);
#pragma unroll
            for (int np = 0; np < 4; np++)
                ldsm4(bf[np], bbase + np * (16 * GPAD * 4) + ks * 32);
#pragma unroll
            for (int mt = 0; mt < 4; mt++)
#pragma unroll
                for (int nt = 0; nt < 8; nt++)
                    mma_tf32(d[mt][nt], af[mt], &bf[nt >> 1][(nt & 1) * 2]);
        }
        __syncthreads();
        if (c + 2 < 16) issue(c + 2, c & 1);
    }

    const int gr = lane >> 2, gc = lane & 3;

    if (MODE == 2) {
        // Stage output tile transposed in smem (bias+resid fused), then write
        // directly to d_out in (B, C, N) layout, fully coalesced.
        float* stile = sm;   // 128 x 132 floats = 67584 B <= 73728 B
#pragma unroll
        for (int mt = 0; mt < 4; mt++) {
#pragma unroll
            for (int half = 0; half < 2; half++) {
                int row = wm + mt * 16 + gr + half * 8;       // local row (n dim)
                int grow = m0 + row;
#pragma unroll
                for (int nt = 0; nt < 8; nt++) {
                    int col = wn + nt * 8 + gc * 2;           // local col (C dim)
                    float2 b2 = *(const float2*)&bias[n0 + col];
                    float2 rr = *(const float2*)&resid[(size_t)grow * 512 + n0 + col];
                    stile[(col + 0) * 132 + row] = d[mt][nt][half * 2 + 0] + b2.x + rr.x;
                    stile[(col + 1) * 132 + row] = d[mt][nt][half * 2 + 1] + b2.y + rr.y;
                }
            }
        }
        __syncthreads();
        int b   = m0 >> 12;
        int nb0 = m0 & 4095;
#pragma unroll
        for (int cc = 0; cc < 32; cc++) {
            int col = w * 32 + cc;
            float4 v = *(float4*)&stile[col * 132 + lane * 4];
            *(float4*)&Cout[((size_t)(b * 512) + n0 + col) * 4096 + nb0 + lane * 4] = v;
        }
    } else {
#pragma unroll
        for (int mt = 0; mt < 4; mt++) {
            int row0 = m0 + wm + mt * 16 + gr;
#pragma unroll
            for (int half = 0; half < 2; half++) {
                int row = row0 + half * 8;
                float* crow = Cout + (size_t)row * 512;
                int pos = row & (ND - 1);
#pragma unroll
                for (int nt = 0; nt < 8; nt++) {
                    int col = n0 + wn + nt * 8 + gc * 2;
                    float2 b2 = *(const float2*)&bias[col];
                    float x0 = d[mt][nt][half * 2 + 0] + b2.x;
                    float x1 = d[mt][nt][half * 2 + 1] + b2.y;
                    float2 o;
                    if (MODE == 1) {
                        float2 sc = g_rope[pos * 32 + ((col & 63) >> 1)];
                        o.x = x0 * sc.y - x1 * sc.x;
                        o.y = x0 * sc.x + x1 * sc.y;
                    } else {
                        o.x = x0;
                        o.y = x1;
                    }
                    *(float2*)&crow[col] = o;
                }
            }
        }
    }
}

// ---------------------------------------------------------------------------
// Windowed attention on tensor cores (TF32 mma.sync).
// grid (64 windows, NH, B), 128 threads (4 warps). One (b,h,window) per CTA.
// Dyn smem: Q[64x68], K[64x68], V^T[64x68], P[64x68] = 69632 B.
// ---------------------------------------------------------------------------
#define APAD 68
#define ATTN_DSMEM (4 * 64 * APAD * 4)

__global__ __launch_bounds__(128) void attn_kernel() {
    extern __shared__ float smd[];
    float* qs  = smd;
    float* ksm = smd + 64 * APAD;
    float* vt  = smd + 2 * 64 * APAD;
    float* ps  = smd + 3 * 64 * APAD;

    int w = blockIdx.x, h = blockIdx.y, b = blockIdx.z;
    int wy = w >> 3, wx = w & 7;
    size_t base = (size_t)b * ND * CD + (size_t)h * 64;
    const float* Qg = g_Qp + base;
    const float* Kg = g_Kp + base;
    const float* Vg = g_Vp + base;

    int t = threadIdx.x;
#pragma unroll
    for (int it = 0; it < 8; it++) {
        int idx = t + it * 128;
        int r = idx >> 4, c4 = idx & 15;               // r = row (q/key), c4 = d/4
        int n = (wy * 8 + (r >> 3)) * 64 + wx * 8 + (r & 7);
        size_t ga = (size_t)n * CD + c4 * 4;
        *(float4*)&qs [r * APAD + c4 * 4] = cvt4(*(const float4*)&Qg[ga]);
        *(float4*)&ksm[r * APAD + c4 * 4] = cvt4(*(const float4*)&Kg[ga]);
        float4 vv = cvt4(*(const float4*)&Vg[ga]);
        vt[(c4 * 4 + 0) * APAD + r] = vv.x;            // transposed: [d][key]
        vt[(c4 * 4 + 1) * APAD + r] = vv.y;
        vt[(c4 * 4 + 2) * APAD + r] = vv.z;
        vt[(c4 * 4 + 3) * APAD + r] = vv.w;
    }
    __syncthreads();

    const int wid = t >> 5, lane = t & 31;
    const int q8 = lane >> 3, r8 = lane & 7;
    uint32_t qsb = smem_u32(qs), ksb = smem_u32(ksm);
    uint32_t vtb = smem_u32(vt), psb = smem_u32(ps);

    uint32_t aoff = (uint32_t)((wid * 16 + ((q8 & 1) << 3) + r8) * APAD + ((q8 >> 1) << 2)) * 4;
    uint32_t boff[4];
#pragma unroll
    for (int np = 0; np < 4; np++)
        boff[np] = (uint32_t)((np * 16 + ((q8 >> 1) << 3) + r8) * APAD + ((q8 & 1) << 2)) * 4;

    // ---- S = Q @ K^T ----
    float s[8][4];
#pragma unroll
    for (int i = 0; i < 8; i++)
#pragma unroll
        for (int j = 0; j < 4; j++) s[i][j] = 0.f;

#pragma unroll
    for (int kc = 0; kc < 8; kc++) {
        uint32_t af[4], bf[4][4];
        ldsm4(af, qsb + aoff + kc * 32);
#pragma unroll
        for (int np = 0; np < 4; np++)
            ldsm4(bf[np], ksb + boff[np] + kc * 32);
#pragma unroll
        for (int nt = 0; nt < 8; nt++)
            mma_tf32(s[nt], af, &bf[nt >> 1][(nt & 1) * 2]);
    }

    // ---- scale + bias + softmax (rows q0 = wid*16+gr, q1 = q0+8) ----
    const int gr = lane >> 2, gc = lane & 3;
    const int q0 = wid * 16 + gr, q1 = q0 + 8;
    const float* br0 = g_biasM + h * 4096 + q0 * 64;
    const float* br1 = g_biasM + h * 4096 + q1 * 64;

    float mx0 = -1e30f, mx1 = -1e30f;
#pragma unroll
    for (int nt = 0; nt < 8; nt++) {
        int col = nt * 8 + gc * 2;
        float2 b0 = *(const float2*)&br0[col];
        float2 b1 = *(const float2*)&br1[col];
        s[nt][0] = s[nt][0] * 0.125f + b0.x;
        s[nt][1] = s[nt][1] * 0.125f + b0.y;
        s[nt][2] = s[nt][2] * 0.125f + b1.x;
        s[nt][3] = s[nt][3] * 0.125f + b1.y;
        mx0 = fmaxf(mx0, fmaxf(s[nt][0], s[nt][1]));
        mx1 = fmaxf(mx1, fmaxf(s[nt][2], s[nt][3]));
    }
    mx0 = fmaxf(mx0, __shfl_xor_sync(~0u, mx0, 1));
    mx0 = fmaxf(mx0, __shfl_xor_sync(~0u, mx0, 2));
    mx1 = fmaxf(mx1, __shfl_xor_sync(~0u, mx1, 1));
    mx1 = fmaxf(mx1, __shfl_xor_sync(~0u, mx1, 2));

    float sum0 = 0.f, sum1 = 0.f;
#pragma unroll
    for (int nt = 0; nt < 8; nt++) {
        s[nt][0] = __expf(s[nt][0] - mx0);
        s[nt][1] = __expf(s[nt][1] - mx0);
        s[nt][2] = __expf(s[nt][2] - mx1);
        s[nt][3] = __expf(s[nt][3] - mx1);
        sum0 += s[nt][0] + s[nt][1];
        sum1 += s[nt][2] + s[nt][3];
    }
    sum0 += __shfl_xor_sync(~0u, sum0, 1);
    sum0 += __shfl_xor_sync(~0u, sum0, 2);
    sum1 += __shfl_xor_sync(~0u, sum1, 1);
    sum1 += __shfl_xor_sync(~0u, sum1, 2);
    float inv0 = 1.0f / sum0, inv1 = 1.0f / sum1;

    // store P row-major (tf32-rounded); P rows are warp-local
#pragma unroll
    for (int nt = 0; nt < 8; nt++) {
        int col = nt * 8 + gc * 2;
        float2 p0 = make_float2(rtf(s[nt][0] * inv0), rtf(s[nt][1] * inv0));
        float2 p1 = make_float2(rtf(s[nt][2] * inv1), rtf(s[nt][3] * inv1));
        *(float2*)&ps[q0 * APAD + col] = p0;
        *(float2*)&ps[q1 * APAD + col] = p1;
    }
    __syncwarp();

    // ---- O = P @ V  (B = V^T stored [d][key]) ----
    float o[8][4];
#pragma unroll
    for (int i = 0; i < 8; i++)
#pragma unroll
        for (int j = 0; j < 4; j++) o[i][j] = 0.f;

#pragma unroll
    for (int kc = 0; kc < 8; kc++) {
        uint32_t af[4], bf[4][4];
        ldsm4(af, psb + aoff + kc * 32);
#pragma unroll
        for (int np = 0; np < 4; np++)
            ldsm4(bf[np], vtb + boff[np] + kc * 32);
#pragma unroll
        for (int nt = 0; nt < 8; nt++)
            mma_tf32(o[nt], af, &bf[nt >> 1][(nt & 1) * 2]);
    }

    // ---- write O (tf32-rounded: it is the A-operand of the O-projection) ----
    float* Ob = g_attn + base;
    int n0t = (wy * 8 + (q0 >> 3)) * 64 + wx * 8 + (q0 & 7);
    int n1t = (wy * 8 + (q1 >> 3)) * 64 + wx * 8 + (q1 & 7);
#pragma unroll
    for (int nt = 0; nt < 8; nt++) {
        int col = nt * 8 + gc * 2;
        *(float2*)&Ob[(size_t)n0t * CD + col] = make_float2(rtf(o[nt][0]), rtf(o[nt][1]));
        *(float2*)&Ob[(size_t)n1t * CD + col] = make_float2(rtf(o[nt][2]), rtf(o[nt][3]));
    }
}

// ---------------------------------------------------------------------------
// Launch
// ---------------------------------------------------------------------------
extern "C" void kernel_launch(void* const* d_in, const int* in_sizes, int n_in,
                              void* d_out, int out_size) {
    const float* q       = (const float*)d_in[0];
    const float* kv      = (const float*)d_in[1];
    const float* g_q     = (const float*)d_in[2];
    const float* b_q_ln  = (const float*)d_in[3];
    const float* g_kv    = (const float*)d_in[4];
    const float* b_kv_ln = (const float*)d_in[5];
    const float* Wq      = (const float*)d_in[6];
    const float* bq      = (const float*)d_in[7];
    const float* Wk      = (const float*)d_in[8];
    const float* bk      = (const float*)d_in[9];
    const float* Wv      = (const float*)d_in[10];
    const float* bv      = (const float*)d_in[11];
    const float* Wo      = (const float*)d_in[12];
    const float* bo      = (const float*)d_in[13];
    const float* btab    = (const float*)d_in[14];
    float* out = (float*)d_out;

    float *qn, *kvn, *Qp, *Kp, *Vp, *att, *wr;
    cudaGetSymbolAddress((void**)&qn,  g_qnorm);
    cudaGetSymbolAddress((void**)&kvn, g_kvnorm);
    cudaGetSymbolAddress((void**)&Qp,  g_Qp);
    cudaGetSymbolAddress((void**)&Kp,  g_Kp);
    cudaGetSymbolAddress((void**)&Vp,  g_Vp);
    cudaGetSymbolAddress((void**)&att, g_attn);
    cudaGetSymbolAddress((void**)&wr,  g_Wr);

    // 1. precompute rope cache + bias matrix + rounded weights
    precompute_kernel<<<512, 256>>>(btab);
    roundw_kernel<<<1024, 256>>>(Wq, Wk, Wv, Wo);

    // 2. LayerNorm q, kv (tf32-rounded outputs)
    ln_kernel<<<2048, 256>>>(q,  g_q,  b_q_ln,  qn);
    ln_kernel<<<2048, 256>>>(kv, g_kv, b_kv_ln, kvn);

    // 3. QKV projections (cp.async + 64x64 warp tiles; rope fused)
    cudaFuncSetAttribute(gemm_mma<0>, cudaFuncAttributeMaxDynamicSharedMemorySize, GEMM_DSMEM);
    cudaFuncSetAttribute(gemm_mma<1>, cudaFuncAttributeMaxDynamicSharedMemorySize, GEMM_DSMEM);
    cudaFuncSetAttribute(gemm_mma<2>, cudaFuncAttributeMaxDynamicSharedMemorySize, GEMM_DSMEM);

    dim3 ggrid(NTOK / 128, 4);
    gemm_mma<1><<<ggrid, 128, GEMM_DSMEM>>>(qn,  wr + 0 * CD * CD, bq, nullptr, Qp);
    gemm_mma<1><<<ggrid, 128, GEMM_DSMEM>>>(kvn, wr + 1 * CD * CD, bk, nullptr, Kp);
    gemm_mma<0><<<ggrid, 128, GEMM_DSMEM>>>(kvn, wr + 2 * CD * CD, bv, nullptr, Vp);

    // 4. windowed attention on tensor cores
    cudaFuncSetAttribute(attn_kernel, cudaFuncAttributeMaxDynamicSharedMemorySize, ATTN_DSMEM);
    attn_kernel<<<dim3(64, NHD, BD), 128, ATTN_DSMEM>>>();

    // 5. output projection + residual, transposed write straight to (B,C,H,W)
    gemm_mma<2><<<ggrid, 128, GEMM_DSMEM>>>(att, wr + 3 * CD * CD, bo, qn, out);
}